// round 1
// baseline (speedup 1.0000x reference)
#include <cuda_runtime.h>
#include <math.h>

#define Bsz 2
#define Lsz 2048
#define Hsz 16
#define Dsz 64
#define HIDsz 1024
#define NBsz 4
#define NPOS (Bsz*Lsz)        // 4096
#define NO 128                // 2*D = W1 output cols
#define BRROWS 256            // branch region rows (4 * 64)
#define NSTAT 12              // 4 branches * (mean, rms, max)
#define BR_ROW0 (HIDsz + 3*Dsz*NBsz)   // 1792

// Static device scratch (no allocation allowed)
__device__ float g_Hc[NPOS * NO];       // 2 MB: hidden-segment contribution per position
__device__ float g_wsum[NSTAT * NO];    // 6 KB: per-stat column sums of W1 stat blocks

// ---------------------------------------------------------------------------
// Kernel 0: Wsum[s][o] = sum over the 64 rows of W1 stat-block s, column o
// ---------------------------------------------------------------------------
__global__ void k_wsum(const float* __restrict__ W1) {
    int idx = blockIdx.x * blockDim.x + threadIdx.x;
    if (idx >= NSTAT * NO) return;
    int s = idx / NO, o = idx % NO;
    const float* p = W1 + (HIDsz + s * Dsz) * NO + o;
    float acc = 0.f;
#pragma unroll
    for (int r = 0; r < Dsz; r++) acc += p[r * NO];
    g_wsum[idx] = acc;
}

// ---------------------------------------------------------------------------
// Kernel 1: Hc[pos][o] = hidden[pos,:] @ W1[0:1024, :]
// Block = 8 positions. Warp-K-split: warp w handles k in [w*128,(w+1)*128),
// all 8 positions; partials reduced through smem. W1 rows read once per block
// (LDG.128, L2-resident since W1 is 1 MB reused by all 512 blocks).
// ---------------------------------------------------------------------------
__global__ void __launch_bounds__(256) k_hidden(const float* __restrict__ hid,
                                                const float* __restrict__ W1) {
    __shared__ float4 Hcp[8][8][32];   // [warp][m][o4] 32 KB
    int tid = threadIdx.x, w = tid >> 5, lane = tid & 31;
    int pos0 = blockIdx.x * 8;

    float4 acc[8];
#pragma unroll
    for (int m = 0; m < 8; m++) acc[m] = make_float4(0.f, 0.f, 0.f, 0.f);

    const float4* W4 = (const float4*)W1;   // W1[k][lane*4..+3] = W4[k*32+lane]
    int kbase = w * 128;
#pragma unroll 4
    for (int kk = 0; kk < 128; kk++) {
        int k = kbase + kk;
        float4 wv = W4[k * 32 + lane];
#pragma unroll
        for (int m = 0; m < 8; m++) {
            float hv = hid[(pos0 + m) * HIDsz + k];   // warp-broadcast load
            acc[m].x += hv * wv.x; acc[m].y += hv * wv.y;
            acc[m].z += hv * wv.z; acc[m].w += hv * wv.w;
        }
    }
#pragma unroll
    for (int m = 0; m < 8; m++) Hcp[w][m][lane] = acc[m];
    __syncthreads();

    // Reduce 8 warp-partials: thread t -> (m = t/32, o4 = t%32)
    int m = tid >> 5, ol = tid & 31;
    float4 s = make_float4(0.f, 0.f, 0.f, 0.f);
#pragma unroll
    for (int wi = 0; wi < 8; wi++) {
        float4 v = Hcp[wi][m][ol];
        s.x += v.x; s.y += v.y; s.z += v.z; s.w += v.w;
    }
    ((float4*)g_Hc)[(pos0 + m) * 32 + ol] = s;
}

// ---------------------------------------------------------------------------
// Kernel 2: per-(pos,head) branch GEMM fragment + stat correction + epilogue.
// Block = 8 positions (1 warp each, 16 heads per warp, 4-head groups).
// W1 branch region (256x128 = 131 KB) staged once in smem.
// ---------------------------------------------------------------------------
__device__ __forceinline__ float gelu_exact(float x) {
    return 0.5f * x * (1.f + erff(x * 0.70710678118654752f));
}

#define SMEM_FLOATS (32768 + 8192 + 1536 + 1024 + 512 + 128 + 64 + 16 + 4)

__global__ void __launch_bounds__(256) k_main(
    const float* __restrict__ br0, const float* __restrict__ br1,
    const float* __restrict__ br2, const float* __restrict__ br3,
    const float* __restrict__ W1,  const float* __restrict__ bias1,
    const float* __restrict__ W2,  const float* __restrict__ bias2,
    const float* __restrict__ epsf, const float* __restrict__ temp,
    float* __restrict__ out)
{
    extern __shared__ float sm[];
    float* sw1b  = sm;               // 32768  W1 branch region [256][128]
    float* sxs   = sw1b + 32768;     // 8192   x staging [8 warps][4 heads][256]
    float* swsum = sxs + 8192;       // 1536
    float* sHc   = swsum + 1536;     // 1024
    float* sW2   = sHc + 1024;       // 512
    float* sb1   = sW2 + 512;        // 128
    float* seps  = sb1 + 128;        // 64
    float* stemp = seps + 64;        // 16
    float* sb2   = stemp + 16;       // 4

    int tid = threadIdx.x, w = tid >> 5, lane = tid & 31;
    int pos0 = blockIdx.x * 8;

    {   // cooperative smem fills
        const float4* g4 = (const float4*)(W1 + BR_ROW0 * NO);
        float4* s4 = (float4*)sw1b;
        for (int i = tid; i < 8192; i += 256) s4[i] = g4[i];
        const float4* h4 = (const float4*)(g_Hc + pos0 * NO);
        ((float4*)sHc)[tid & 255] = h4[tid & 255];          // 256 float4
        const float4* ws4 = (const float4*)g_wsum;
        float4* sws4 = (float4*)swsum;
        for (int i = tid; i < 384; i += 256) sws4[i] = ws4[i];
        if (tid < 128) ((float4*)sW2)[tid] = ((const float4*)W2)[tid];
        if (tid < 128) sb1[tid] = bias1[tid];
        if (tid < 64)  seps[tid] = epsf[tid];
        if (tid < 16)  stemp[tid] = temp[tid];
        if (tid < 4)   sb2[tid] = bias2[tid];
    }
    __syncthreads();

    int pos = pos0 + w;
    float4 hc = ((float4*)sHc)[w * 32 + lane];
    float4 bb = ((float4*)sb1)[lane];
    float4 base0 = make_float4(hc.x + bb.x, hc.y + bb.y, hc.z + bb.z, hc.w + bb.w);

    float* xw = sxs + w * 1024;                 // this warp's [4][256] x stage
    const float4* w1b4  = (const float4*)sw1b;
    const float4* wsum4 = (const float4*)swsum;
    const float4* w2r4  = (const float4*)sW2;   // W2 row per o: 4 logits

    for (int grp = 0; grp < 4; grp++) {
        float4 acc[4];

#pragma unroll
        for (int q = 0; q < 4; q++) {
            int h = grp * 4 + q;
            size_t rbase = ((size_t)pos * Hsz + h) * Dsz;
            float2 v0 = ((const float2*)(br0 + rbase))[lane];
            float2 v1 = ((const float2*)(br1 + rbase))[lane];
            float2 v2 = ((const float2*)(br2 + rbase))[lane];
            float2 v3 = ((const float2*)(br3 + rbase))[lane];
            ((float2*)(xw + q * 256 +   0))[lane] = v0;
            ((float2*)(xw + q * 256 +  64))[lane] = v1;
            ((float2*)(xw + q * 256 + 128))[lane] = v2;
            ((float2*)(xw + q * 256 + 192))[lane] = v3;

            float s0 = v0.x + v0.y, q0 = v0.x*v0.x + v0.y*v0.y, m0 = fmaxf(v0.x, v0.y);
            float s1 = v1.x + v1.y, q1 = v1.x*v1.x + v1.y*v1.y, m1 = fmaxf(v1.x, v1.y);
            float s2 = v2.x + v2.y, q2 = v2.x*v2.x + v2.y*v2.y, m2 = fmaxf(v2.x, v2.y);
            float s3 = v3.x + v3.y, q3 = v3.x*v3.x + v3.y*v3.y, m3 = fmaxf(v3.x, v3.y);
#pragma unroll
            for (int off = 16; off; off >>= 1) {
                s0 += __shfl_xor_sync(0xffffffffu, s0, off);
                q0 += __shfl_xor_sync(0xffffffffu, q0, off);
                m0 = fmaxf(m0, __shfl_xor_sync(0xffffffffu, m0, off));
                s1 += __shfl_xor_sync(0xffffffffu, s1, off);
                q1 += __shfl_xor_sync(0xffffffffu, q1, off);
                m1 = fmaxf(m1, __shfl_xor_sync(0xffffffffu, m1, off));
                s2 += __shfl_xor_sync(0xffffffffu, s2, off);
                q2 += __shfl_xor_sync(0xffffffffu, q2, off);
                m2 = fmaxf(m2, __shfl_xor_sync(0xffffffffu, m2, off));
                s3 += __shfl_xor_sync(0xffffffffu, s3, off);
                q3 += __shfl_xor_sync(0xffffffffu, q3, off);
                m3 = fmaxf(m3, __shfl_xor_sync(0xffffffffu, m3, off));
            }
            const float inv64 = 1.f / 64.f;
            float st[12];
            st[0] = s0 * inv64; st[1] = sqrtf(fmaxf(q0 * inv64, 1e-8f)); st[2]  = m0;
            st[3] = s1 * inv64; st[4] = sqrtf(fmaxf(q1 * inv64, 1e-8f)); st[5]  = m1;
            st[6] = s2 * inv64; st[7] = sqrtf(fmaxf(q2 * inv64, 1e-8f)); st[8]  = m2;
            st[9] = s3 * inv64; st[10]= sqrtf(fmaxf(q3 * inv64, 1e-8f)); st[11] = m3;

            float4 a = base0;
#pragma unroll
            for (int s = 0; s < 12; s++) {
                float4 wv = wsum4[s * 32 + lane];
                a.x += st[s] * wv.x; a.y += st[s] * wv.y;
                a.z += st[s] * wv.z; a.w += st[s] * wv.w;
            }
            acc[q] = a;
        }
        __syncwarp();

        // Branch-region dot: acc[q][o4] += x[q][r] * W1b[r][o4]
#pragma unroll 4
        for (int r = 0; r < BRROWS; r++) {
            float4 wv = w1b4[r * 32 + lane];
#pragma unroll
            for (int q = 0; q < 4; q++) {
                float xv = xw[q * 256 + r];
                acc[q].x += xv * wv.x; acc[q].y += xv * wv.y;
                acc[q].z += xv * wv.z; acc[q].w += xv * wv.w;
            }
        }
        __syncwarp();   // xs reused by next group

        // Epilogue per head: gelu -> W2 -> reduce -> softmax/temp/floor/renorm
#pragma unroll
        for (int q = 0; q < 4; q++) {
            int h = grp * 4 + q;
            float g0 = gelu_exact(acc[q].x);
            float g1 = gelu_exact(acc[q].y);
            float g2 = gelu_exact(acc[q].z);
            float g3 = gelu_exact(acc[q].w);
            int o0 = lane * 4;
            float4 lp = make_float4(0.f, 0.f, 0.f, 0.f);
            float4 r0 = w2r4[o0 + 0];
            float4 r1 = w2r4[o0 + 1];
            float4 r2 = w2r4[o0 + 2];
            float4 r3 = w2r4[o0 + 3];
            lp.x = g0*r0.x + g1*r1.x + g2*r2.x + g3*r3.x;
            lp.y = g0*r0.y + g1*r1.y + g2*r2.y + g3*r3.y;
            lp.z = g0*r0.z + g1*r1.z + g2*r2.z + g3*r3.z;
            lp.w = g0*r0.w + g1*r1.w + g2*r2.w + g3*r3.w;
#pragma unroll
            for (int off = 16; off; off >>= 1) {
                lp.x += __shfl_xor_sync(0xffffffffu, lp.x, off);
                lp.y += __shfl_xor_sync(0xffffffffu, lp.y, off);
                lp.z += __shfl_xor_sync(0xffffffffu, lp.z, off);
                lp.w += __shfl_xor_sync(0xffffffffu, lp.w, off);
            }
            if (lane == 0) {
                float t  = fminf(fmaxf(stemp[h], 0.2f), 10.f);
                float it = 1.f / t;
                float l0 = (lp.x + sb2[0]) * it;
                float l1 = (lp.y + sb2[1]) * it;
                float l2 = (lp.z + sb2[2]) * it;
                float l3 = (lp.w + sb2[3]) * it;
                float mx = fmaxf(fmaxf(l0, l1), fmaxf(l2, l3));
                float e0 = expf(l0 - mx), e1 = expf(l1 - mx);
                float e2 = expf(l2 - mx), e3 = expf(l3 - mx);
                float is = 1.f / (e0 + e1 + e2 + e3);
                float w0 = e0 * is, w1v = e1 * is, w2v = e2 * is, w3v = e3 * is;
                w0  = fmaxf(w0,  fminf(fmaxf(seps[h*4+0], 1e-7f), 0.1f));
                w1v = fmaxf(w1v, fminf(fmaxf(seps[h*4+1], 1e-7f), 0.1f));
                w2v = fmaxf(w2v, fminf(fmaxf(seps[h*4+2], 1e-7f), 0.1f));
                w3v = fmaxf(w3v, fminf(fmaxf(seps[h*4+3], 1e-7f), 0.1f));
                float inv = 1.f / (w0 + w1v + w2v + w3v);
                ((float4*)out)[pos * Hsz + h] =
                    make_float4(w0 * inv, w1v * inv, w2v * inv, w3v * inv);
            }
        }
    }
}

// ---------------------------------------------------------------------------
extern "C" void kernel_launch(void* const* d_in, const int* in_sizes, int n_in,
                              void* d_out, int out_size)
{
    const float* hidden = (const float*)d_in[0];
    const float* br0    = (const float*)d_in[1];
    const float* br1    = (const float*)d_in[2];
    const float* br2    = (const float*)d_in[3];
    const float* br3    = (const float*)d_in[4];
    const float* W1     = (const float*)d_in[5];
    const float* bias1  = (const float*)d_in[6];
    const float* W2     = (const float*)d_in[7];
    const float* bias2  = (const float*)d_in[8];
    const float* epsf   = (const float*)d_in[9];
    const float* temp   = (const float*)d_in[10];

    const int smem_bytes = SMEM_FLOATS * (int)sizeof(float);   // ~177 KB
    cudaFuncSetAttribute(k_main, cudaFuncAttributeMaxDynamicSharedMemorySize, smem_bytes);

    k_wsum<<<6, 256>>>(W1);
    k_hidden<<<NPOS / 8, 256>>>(hidden, W1);
    k_main<<<NPOS / 8, 256, smem_bytes>>>(br0, br1, br2, br3, W1, bias1, W2, bias2,
                                          epsf, temp, (float*)d_out);
}